// round 11
// baseline (speedup 1.0000x reference)
#include <cuda_runtime.h>
#include <cuda_bf16.h>
#include <cstdint>

// CenterLoss: out = mean_i clamp(||x[i] - centers[labels[i]]||^2, 1e-12, 1e12)
// x: (16384, 2048) f32, labels: (16384,) int32 (harness narrows int64->int32),
// centers: (751, 2048) f32
// Inputs per metadata order: d_in[0]=x, d_in[1]=labels, d_in[2]=centers.
//
// Single fused kernel: per-CTA row distances + last-CTA-done deterministic
// final reduction (atomicInc ticket wraps to 0 -> graph-replay safe).

#define B_ROWS 16384
#define D_DIM  2048
#define D_VEC  (D_DIM / 4)            // 512 float4 per row
#define TPB    128                    // threads per block
#define ROWS_PER_CTA 2
#define NUM_CTAS (B_ROWS / ROWS_PER_CTA)
#define F4_PER_THREAD (D_VEC / TPB)   // 4 float4 per row per thread
#define PARTIAL_F4 (B_ROWS / 4)       // 4096 float4 of partials
#define F4_PER_THREAD_RED (PARTIAL_F4 / TPB)  // 32

__device__ float g_partial[B_ROWS];
__device__ unsigned int g_count;      // zero-init; wraps back to 0 each launch

// Streaming (evict-first) float4 load: keeps the one-pass x stream from
// evicting the heavily-reused centers working set (6.2 MB) out of L2.
__device__ __forceinline__ float4 ldcs_f4(const float4* p) {
    float4 v;
    asm volatile("ld.global.cs.v4.f32 {%0,%1,%2,%3}, [%4];"
                 : "=f"(v.x), "=f"(v.y), "=f"(v.z), "=f"(v.w)
                 : "l"(p));
    return v;
}

__global__ __launch_bounds__(TPB) void center_loss_fused_kernel(
    const float4* __restrict__ x,
    const int* __restrict__ labels,
    const float4* __restrict__ centers,
    float* __restrict__ out)
{
    const int row0 = blockIdx.x * ROWS_PER_CTA;
    const int row1 = row0 + 1;
    const int t = threadIdx.x;

    const float4* __restrict__ xr0 = x + (size_t)row0 * D_VEC;
    const float4* __restrict__ xr1 = x + (size_t)row1 * D_VEC;
    const int lab0 = labels[row0];
    const int lab1 = labels[row1];
    const float4* __restrict__ cr0 = centers + (size_t)lab0 * D_VEC;
    const float4* __restrict__ cr1 = centers + (size_t)lab1 * D_VEC;

    // Front-batch 16 independent LDG.128 per thread:
    // 8 x-stream loads (2 rows x 4) + 8 centers loads (2 rows x 4).
    float4 a0[F4_PER_THREAD], a1[F4_PER_THREAD];
    float4 b0[F4_PER_THREAD], b1[F4_PER_THREAD];
    #pragma unroll
    for (int i = 0; i < F4_PER_THREAD; i++) a0[i] = ldcs_f4(&xr0[t + i * TPB]);
    #pragma unroll
    for (int i = 0; i < F4_PER_THREAD; i++) a1[i] = ldcs_f4(&xr1[t + i * TPB]);
    #pragma unroll
    for (int i = 0; i < F4_PER_THREAD; i++) b0[i] = __ldg(&cr0[t + i * TPB]);
    #pragma unroll
    for (int i = 0; i < F4_PER_THREAD; i++) b1[i] = __ldg(&cr1[t + i * TPB]);

    float acc0 = 0.0f, acc1 = 0.0f;
    #pragma unroll
    for (int i = 0; i < F4_PER_THREAD; i++) {
        float d;
        d = a0[i].x - b0[i].x; acc0 = fmaf(d, d, acc0);
        d = a0[i].y - b0[i].y; acc0 = fmaf(d, d, acc0);
        d = a0[i].z - b0[i].z; acc0 = fmaf(d, d, acc0);
        d = a0[i].w - b0[i].w; acc0 = fmaf(d, d, acc0);
        d = a1[i].x - b1[i].x; acc1 = fmaf(d, d, acc1);
        d = a1[i].y - b1[i].y; acc1 = fmaf(d, d, acc1);
        d = a1[i].z - b1[i].z; acc1 = fmaf(d, d, acc1);
        d = a1[i].w - b1[i].w; acc1 = fmaf(d, d, acc1);
    }

    // Warp reduce both rows
    #pragma unroll
    for (int off = 16; off > 0; off >>= 1) {
        acc0 += __shfl_down_sync(0xFFFFFFFFu, acc0, off);
        acc1 += __shfl_down_sync(0xFFFFFFFFu, acc1, off);
    }

    // Block reduce across 4 warps, both rows
    __shared__ float warp_sums0[TPB / 32];
    __shared__ float warp_sums1[TPB / 32];
    const int wid = t >> 5;
    const int lid = t & 31;
    if (lid == 0) { warp_sums0[wid] = acc0; warp_sums1[wid] = acc1; }
    __syncthreads();

    if (t == 0) {
        float v0 = warp_sums0[0] + warp_sums0[1] + warp_sums0[2] + warp_sums0[3];
        float v1 = warp_sums1[0] + warp_sums1[1] + warp_sums1[2] + warp_sums1[3];
        // clamp per-row before the mean (matches reference semantics)
        v0 = fminf(fmaxf(v0, 1e-12f), 1e12f);
        v1 = fminf(fmaxf(v1, 1e-12f), 1e12f);
        __stcg(&g_partial[row0], v0);   // L1-bypass: L2-coherent for last CTA
        __stcg(&g_partial[row1], v1);
    }

    // --- last-CTA-done final reduction ---
    __shared__ int is_last;
    if (t == 0) {
        __threadfence();  // partials visible before ticket
        unsigned int ticket = atomicInc(&g_count, NUM_CTAS - 1);  // wraps to 0
        is_last = (ticket == NUM_CTAS - 1) ? 1 : 0;
    }
    __syncthreads();
    if (!is_last) return;

    // Fixed-order reduction of all 16384 partials -> bitwise deterministic.
    const float4* __restrict__ p4 = (const float4*)g_partial;
    float acc = 0.0f;
    #pragma unroll
    for (int i = 0; i < F4_PER_THREAD_RED; i++) {
        float4 v = __ldcg(&p4[t + i * TPB]);
        acc += (v.x + v.y) + (v.z + v.w);
    }

    #pragma unroll
    for (int off = 16; off > 0; off >>= 1)
        acc += __shfl_down_sync(0xFFFFFFFFu, acc, off);

    __shared__ float red_sums[TPB / 32];
    if (lid == 0) red_sums[wid] = acc;
    __syncthreads();

    if (t == 0) {
        float total = red_sums[0] + red_sums[1] + red_sums[2] + red_sums[3];
        out[0] = total * (1.0f / (float)B_ROWS);
    }
}

extern "C" void kernel_launch(void* const* d_in, const int* in_sizes, int n_in,
                              void* d_out, int out_size)
{
    const float4* x       = (const float4*)d_in[0];
    const int*    labels  = (const int*)d_in[1];
    const float4* centers = (const float4*)d_in[2];
    float*        out     = (float*)d_out;

    center_loss_fused_kernel<<<NUM_CTAS, TPB>>>(x, labels, centers, out);
}

// round 17
// speedup vs baseline: 1.0978x; 1.0978x over previous
#include <cuda_runtime.h>
#include <cuda_bf16.h>
#include <cstdint>

// CenterLoss: out = mean_i clamp(||x[i] - centers[labels[i]]||^2, 1e-12, 1e12)
// x: (16384, 2048) f32, labels: (16384,) int32, centers: (751, 2048) f32
// d_in[0]=x, d_in[1]=labels, d_in[2]=centers.
//
// Persistent-ish fused kernel: 888 CTAs, each loops over 9-10 row-pairs
// (no per-iteration barrier), then ONE fence+atomic per CTA (amortized).
// Last CTA does a fixed-order deterministic final reduction.

#define B_ROWS    16384
#define D_DIM     2048
#define D_VEC     (D_DIM / 4)        // 512 float4 per row
#define TPB       128
#define NUM_CTAS  888                // 148 SMs x 6 CTAs: all resident wave-1
#define N_PAIRS   (B_ROWS / 2)       // 8192 row-pairs
#define BASE_P    (N_PAIRS / NUM_CTAS)          // 9
#define EXTRA     (N_PAIRS - BASE_P * NUM_CTAS) // 200 CTAs do 10 pairs
#define MAX_ROWS  ((BASE_P + 1) * 2)            // 20 rows per CTA max
#define F4_PT     (D_VEC / TPB)      // 4 float4 per row per thread

__device__ float g_partial[NUM_CTAS];
__device__ unsigned int g_count;     // zero-init; wraps to 0 each launch

// Streaming (evict-first) load: keeps the one-pass x stream from evicting
// the heavily-reused centers working set (6.2 MB) out of L2.
__device__ __forceinline__ float4 ldcs_f4(const float4* p) {
    float4 v;
    asm volatile("ld.global.cs.v4.f32 {%0,%1,%2,%3}, [%4];"
                 : "=f"(v.x), "=f"(v.y), "=f"(v.z), "=f"(v.w)
                 : "l"(p));
    return v;
}

__global__ __launch_bounds__(TPB, 6) void center_loss_persistent_kernel(
    const float4* __restrict__ x,
    const int* __restrict__ labels,
    const float4* __restrict__ centers,
    float* __restrict__ out)
{
    const int c = blockIdx.x;
    const int t = threadIdx.x;
    const int wid = t >> 5;
    const int lid = t & 31;

    // Contiguous pair assignment with remainder-first split (per-SM balanced
    // under contiguous-modular CTA->SM placement).
    int n_pairs, first_pair;
    if (c < EXTRA) { n_pairs = BASE_P + 1; first_pair = c * (BASE_P + 1); }
    else           { n_pairs = BASE_P;     first_pair = EXTRA * (BASE_P + 1) + (c - EXTRA) * BASE_P; }

    // Per-(warp,row) sums; unique slots -> no per-iteration barrier needed.
    __shared__ float wsums[TPB / 32][MAX_ROWS];

    for (int p = 0; p < n_pairs; p++) {
        const int row0 = (first_pair + p) * 2;
        const int row1 = row0 + 1;

        const float4* __restrict__ xr0 = x + (size_t)row0 * D_VEC;
        const float4* __restrict__ xr1 = x + (size_t)row1 * D_VEC;
        const int lab0 = __ldg(&labels[row0]);
        const int lab1 = __ldg(&labels[row1]);
        const float4* __restrict__ cr0 = centers + (size_t)lab0 * D_VEC;
        const float4* __restrict__ cr1 = centers + (size_t)lab1 * D_VEC;

        // Front-batch 16 independent LDG.128 per thread.
        float4 a0[F4_PT], a1[F4_PT], b0[F4_PT], b1[F4_PT];
        #pragma unroll
        for (int i = 0; i < F4_PT; i++) a0[i] = ldcs_f4(&xr0[t + i * TPB]);
        #pragma unroll
        for (int i = 0; i < F4_PT; i++) a1[i] = ldcs_f4(&xr1[t + i * TPB]);
        #pragma unroll
        for (int i = 0; i < F4_PT; i++) b0[i] = __ldg(&cr0[t + i * TPB]);
        #pragma unroll
        for (int i = 0; i < F4_PT; i++) b1[i] = __ldg(&cr1[t + i * TPB]);

        float acc0 = 0.0f, acc1 = 0.0f;
        #pragma unroll
        for (int i = 0; i < F4_PT; i++) {
            float d;
            d = a0[i].x - b0[i].x; acc0 = fmaf(d, d, acc0);
            d = a0[i].y - b0[i].y; acc0 = fmaf(d, d, acc0);
            d = a0[i].z - b0[i].z; acc0 = fmaf(d, d, acc0);
            d = a0[i].w - b0[i].w; acc0 = fmaf(d, d, acc0);
            d = a1[i].x - b1[i].x; acc1 = fmaf(d, d, acc1);
            d = a1[i].y - b1[i].y; acc1 = fmaf(d, d, acc1);
            d = a1[i].z - b1[i].z; acc1 = fmaf(d, d, acc1);
            d = a1[i].w - b1[i].w; acc1 = fmaf(d, d, acc1);
        }

        // Warp reduce; lane 0 stores to this row's private smem slot.
        #pragma unroll
        for (int off = 16; off > 0; off >>= 1) {
            acc0 += __shfl_down_sync(0xFFFFFFFFu, acc0, off);
            acc1 += __shfl_down_sync(0xFFFFFFFFu, acc1, off);
        }
        if (lid == 0) {
            wsums[wid][2 * p]     = acc0;
            wsums[wid][2 * p + 1] = acc1;
        }
    }

    __syncthreads();

    // One serial epilogue per CTA (amortized over ~9 iterations).
    __shared__ int is_last;
    if (t == 0) {
        float s = 0.0f;
        const int n_rows = n_pairs * 2;
        for (int r = 0; r < n_rows; r++) {
            float v = wsums[0][r] + wsums[1][r] + wsums[2][r] + wsums[3][r];
            v = fminf(fmaxf(v, 1e-12f), 1e12f);   // clamp per row
            s += v;
        }
        __stcg(&g_partial[c], s);
        __threadfence();
        unsigned int ticket = atomicInc(&g_count, NUM_CTAS - 1);  // wraps to 0
        is_last = (ticket == NUM_CTAS - 1) ? 1 : 0;
    }
    __syncthreads();
    if (!is_last) return;

    // Last CTA: fixed-order reduction of 888 partials -> deterministic.
    float acc = 0.0f;
    for (int i = t; i < NUM_CTAS; i += TPB)
        acc += __ldcg(&g_partial[i]);

    #pragma unroll
    for (int off = 16; off > 0; off >>= 1)
        acc += __shfl_down_sync(0xFFFFFFFFu, acc, off);

    __shared__ float red_sums[TPB / 32];
    if (lid == 0) red_sums[wid] = acc;
    __syncthreads();

    if (t == 0) {
        float total = red_sums[0] + red_sums[1] + red_sums[2] + red_sums[3];
        out[0] = total * (1.0f / (float)B_ROWS);
    }
}

extern "C" void kernel_launch(void* const* d_in, const int* in_sizes, int n_in,
                              void* d_out, int out_size)
{
    const float4* x       = (const float4*)d_in[0];
    const int*    labels  = (const int*)d_in[1];
    const float4* centers = (const float4*)d_in[2];
    float*        out     = (float*)d_out;

    center_loss_persistent_kernel<<<NUM_CTAS, TPB>>>(x, labels, centers, out);
}